// round 1
// baseline (speedup 1.0000x reference)
#include <cuda_runtime.h>
#include <cuda_fp16.h>
#include <cstdint>

// ---------------- constants ----------------
constexpr int TILE    = 64;     // edges per tile
constexpr int THREADS = 256;    // 8 warps

constexpr int LDW = 136;        // weight smem stride (halfs): 272B -> conflict-free ldmatrix.trans
constexpr int LDX = 200;        // X tile stride (halfs): 400B
constexpr int LDH = 72;         // H/G stride
constexpr int LDP = 66;         // Ph/Pg stride

// byte offsets into dynamic smem
constexpr int B_W1E = 0;                         // [192][136] half
constexpr int B_W2E = B_W1E + 192*LDW*2;         // [64][136]
constexpr int B_W1N = B_W2E + 64*LDW*2;
constexpr int B_W2N = B_W1N + 192*LDW*2;
constexpr int B_X   = B_W2N + 64*LDW*2;          // [64][200] half
constexpr int B_H   = B_X   + 64*LDX*2;          // [64][72] half
constexpr int B_G   = B_H   + 64*LDH*2;
constexpr int B_PH  = B_G   + 64*LDH*2;          // [64][66] half
constexpr int B_PG  = B_PH  + 64*LDP*2;
constexpr int B_B1E = B_PG  + 64*LDP*2;          // [128] float each
constexpr int B_B2E = B_B1E + 128*4;
constexpr int B_B1N = B_B2E + 128*4;
constexpr int B_B2N = B_B1N + 128*4;
constexpr int B_RBF = B_B2N + 128*4;             // [64][10] float
constexpr int B_WE  = B_RBF + 64*10*4;           // [64][9] float
constexpr int B_WN  = B_WE  + 64*9*4;
constexpr int SMEM_BYTES = B_WN + 64*9*4;        // = 209408

__device__ __forceinline__ float fsigmoid(float x) { return 1.0f / (1.0f + __expf(-x)); }

// one warp computes a 16x64 slab of a 64x128 GEMM (C = A[64xK] * B[KxN]^T-ish),
// B stored row-major [K][128+pad] fp16, adds bias, applies activation, stores fp16.
// ACT: 0 = silu, 1 = sigmoid.
template <int ACT, int KT>
__device__ __forceinline__ void gemm64(
    const __half* __restrict__ A, int lda,
    const __half* __restrict__ B,
    const float*  __restrict__ bias,
    __half* __restrict__ Dst, int ldd,
    int lane, int mrow, int bcol)
{
    float acc[8][4];
    #pragma unroll
    for (int i = 0; i < 8; ++i)
        #pragma unroll
        for (int j = 0; j < 4; ++j) acc[i][j] = 0.0f;

    uint32_t aAddr = (uint32_t)__cvta_generic_to_shared(
        A + (mrow + (lane & 15)) * lda + ((lane >> 4) << 3));
    uint32_t bAddr = (uint32_t)__cvta_generic_to_shared(
        B + (lane & 15) * LDW + bcol);

    #pragma unroll
    for (int kt = 0; kt < KT; ++kt) {
        uint32_t a0, a1, a2, a3;
        asm volatile("ldmatrix.sync.aligned.m8n8.x4.shared.b16 {%0,%1,%2,%3}, [%4];\n"
                     : "=r"(a0), "=r"(a1), "=r"(a2), "=r"(a3)
                     : "r"(aAddr + kt * 32));
        uint32_t bk = bAddr + kt * (16 * LDW * 2);
        #pragma unroll
        for (int nt = 0; nt < 8; ++nt) {
            uint32_t b0, b1;
            asm volatile("ldmatrix.sync.aligned.m8n8.x2.trans.shared.b16 {%0,%1}, [%2];\n"
                         : "=r"(b0), "=r"(b1) : "r"(bk + nt * 16));
            asm volatile("mma.sync.aligned.m16n8k16.row.col.f32.f16.f16.f32 "
                         "{%0,%1,%2,%3}, {%4,%5,%6,%7}, {%8,%9}, {%0,%1,%2,%3};\n"
                         : "+f"(acc[nt][0]), "+f"(acc[nt][1]), "+f"(acc[nt][2]), "+f"(acc[nt][3])
                         : "r"(a0), "r"(a1), "r"(a2), "r"(a3), "r"(b0), "r"(b1));
        }
    }

    int r0 = mrow + (lane >> 2);
    int cp = (lane & 3) << 1;
    #pragma unroll
    for (int nt = 0; nt < 8; ++nt) {
        int col = nt * 8 + cp;
        float bb0 = bias[bcol + col], bb1 = bias[bcol + col + 1];
        float v00 = acc[nt][0] + bb0, v01 = acc[nt][1] + bb1;
        float v10 = acc[nt][2] + bb0, v11 = acc[nt][3] + bb1;
        if (ACT == 0) {
            v00 *= fsigmoid(v00); v01 *= fsigmoid(v01);
            v10 *= fsigmoid(v10); v11 *= fsigmoid(v11);
        } else {
            v00 = fsigmoid(v00); v01 = fsigmoid(v01);
            v10 = fsigmoid(v10); v11 = fsigmoid(v11);
        }
        *(__half2*)(Dst + r0 * ldd + col)        = __floats2half2_rn(v00, v01);
        *(__half2*)(Dst + (r0 + 8) * ldd + col)  = __floats2half2_rn(v10, v11);
    }
}

__device__ __forceinline__ void st4h(__half* p, float4 v) {
    *(__half2*)(p)     = __floats2half2_rn(v.x, v.y);
    *(__half2*)(p + 2) = __floats2half2_rn(v.z, v.w);
}

__global__ void __launch_bounds__(THREADS, 1) m3gnet_fused(
    const float* __restrict__ node_feat, const float* __restrict__ edge_feat,
    const float* __restrict__ rbf, const int* __restrict__ src, const int* __restrict__ dst,
    const float* __restrict__ el1w, const float* __restrict__ el1b,
    const float* __restrict__ el2w, const float* __restrict__ el2b,
    const float* __restrict__ eg1w, const float* __restrict__ eg1b,
    const float* __restrict__ eg2w, const float* __restrict__ eg2b,
    const float* __restrict__ nl1w, const float* __restrict__ nl1b,
    const float* __restrict__ nl2w, const float* __restrict__ nl2b,
    const float* __restrict__ ng1w, const float* __restrict__ ng1b,
    const float* __restrict__ ng2w, const float* __restrict__ ng2b,
    const float* __restrict__ eww, const float* __restrict__ nww,
    float* __restrict__ out_e, float* __restrict__ out_v,
    int E, int ntiles)
{
    extern __shared__ char smem[];
    __half* s_w1e = (__half*)(smem + B_W1E);
    __half* s_w2e = (__half*)(smem + B_W2E);
    __half* s_w1n = (__half*)(smem + B_W1N);
    __half* s_w2n = (__half*)(smem + B_W2N);
    __half* s_x   = (__half*)(smem + B_X);
    __half* s_h   = (__half*)(smem + B_H);
    __half* s_g   = (__half*)(smem + B_G);
    __half* s_ph  = (__half*)(smem + B_PH);
    __half* s_pg  = (__half*)(smem + B_PG);
    float*  s_b1e = (float*)(smem + B_B1E);
    float*  s_b2e = (float*)(smem + B_B2E);
    float*  s_b1n = (float*)(smem + B_B1N);
    float*  s_b2n = (float*)(smem + B_B2N);
    float*  s_rbf = (float*)(smem + B_RBF);
    float*  s_we  = (float*)(smem + B_WE);
    float*  s_wn  = (float*)(smem + B_WN);

    const int tid = threadIdx.x;

    // ---- one-time weight staging (persistent block amortizes this) ----
    for (int i = tid; i < 64 * 192; i += THREADS) {
        int n = i / 192, k = i - n * 192;
        s_w1e[k * LDW + n]      = __float2half(el1w[i]);
        s_w1e[k * LDW + 64 + n] = __float2half(eg1w[i]);
        s_w1n[k * LDW + n]      = __float2half(nl1w[i]);
        s_w1n[k * LDW + 64 + n] = __float2half(ng1w[i]);
    }
    for (int i = tid; i < 64 * 64; i += THREADS) {
        int n = i / 64, k = i - n * 64;
        s_w2e[k * LDW + n]      = __float2half(el2w[i]);
        s_w2e[k * LDW + 64 + n] = __float2half(eg2w[i]);
        s_w2n[k * LDW + n]      = __float2half(nl2w[i]);
        s_w2n[k * LDW + 64 + n] = __float2half(ng2w[i]);
    }
    if (tid < 64) {
        s_b1e[tid] = el1b[tid]; s_b1e[64 + tid] = eg1b[tid];
        s_b2e[tid] = el2b[tid]; s_b2e[64 + tid] = eg2b[tid];
        s_b1n[tid] = nl1b[tid]; s_b1n[64 + tid] = ng1b[tid];
        s_b2n[tid] = nl2b[tid]; s_b2n[64 + tid] = ng2b[tid];
    }
    for (int i = tid; i < 64 * 9; i += THREADS) {
        s_we[i] = eww[i]; s_wn[i] = nww[i];
    }
    __syncthreads();

    const int lane  = tid & 31;
    const int warp  = tid >> 5;
    const int mrow  = (warp & 3) << 4;   // 0,16,32,48
    const int nhalf = warp >> 2;         // 0 = layers(H), 1 = gates(G)
    const int r  = tid >> 2;             // edge row within tile
    const int l4 = tid & 3;

    for (int t = blockIdx.x; t < ntiles; t += gridDim.x) {
        const long ebase = (long)t * TILE;
        const long e = ebase + r;
        const bool valid = (e < E);
        int de = 0;

        // ---- stage X = [vi | vj | edge_feat] as fp16, and rbf tile ----
        if (valid) {
            const int se = src[e];
            de = dst[e];
            const float4* vs  = (const float4*)(node_feat + (long)se * 64);
            const float4* vd  = (const float4*)(node_feat + (long)de * 64);
            const float4* ef4 = (const float4*)(edge_feat + e * 64);
            #pragma unroll
            for (int j = 0; j < 4; ++j) {
                int f4 = l4 * 4 + j;
                st4h(s_x + r * LDX +        f4 * 4, vs[f4]);
                st4h(s_x + r * LDX + 64  +  f4 * 4, vd[f4]);
                st4h(s_x + r * LDX + 128 +  f4 * 4, ef4[f4]);
            }
        } else {
            const uint2 z = {0u, 0u};
            #pragma unroll
            for (int j = 0; j < 4; ++j) {
                int f4 = l4 * 4 + j;
                *(uint2*)(s_x + r * LDX +       f4 * 4) = z;
                *(uint2*)(s_x + r * LDX + 64  + f4 * 4) = z;
                *(uint2*)(s_x + r * LDX + 128 + f4 * 4) = z;
            }
        }
        for (int i = tid; i < TILE * 9; i += THREADS) {
            int rr = i / 9, kk = i - rr * 9;
            s_rbf[rr * 10 + kk] = (ebase + rr < E) ? rbf[ebase * 9 + i] : 0.0f;
        }
        __syncthreads();

        // ================= EDGE PATH =================
        gemm64<0, 12>(s_x, LDX, s_w1e, s_b1e, nhalf ? s_g : s_h, LDH, lane, mrow, nhalf * 64);
        __syncwarp();
        if (nhalf == 0) gemm64<0, 4>(s_h, LDH, s_w2e, s_b2e, s_ph, LDP, lane, mrow, 0);
        else            gemm64<1, 4>(s_g, LDH, s_w2e, s_b2e, s_pg, LDP, lane, mrow, 64);
        __syncthreads();

        if (valid) {
            const float4* ef4 = (const float4*)(edge_feat + e * 64);
            float4*       oe4 = (float4*)(out_e + e * 64);
            #pragma unroll
            for (int j = 0; j < 4; ++j) {
                int c0 = l4 * 16 + j * 4;
                float4 ef = ef4[c0 >> 2];
                float u[4];
                #pragma unroll
                for (int i = 0; i < 4; ++i) {
                    int cc = c0 + i;
                    const float* wr = s_we + cc * 9;
                    float s = 0.0f;
                    #pragma unroll
                    for (int k = 0; k < 9; ++k) s += s_rbf[r * 10 + k] * wr[k];
                    u[i] = __half2float(s_ph[r * LDP + cc]) *
                           __half2float(s_pg[r * LDP + cc]) * s;
                }
                float4 o;
                o.x = ef.x + u[0]; o.y = ef.y + u[1];
                o.z = ef.z + u[2]; o.w = ef.w + u[3];
                oe4[c0 >> 2] = o;
                // patch e_new into X for the node path
                *(__half2*)(s_x + r * LDX + 128 + c0)     = __floats2half2_rn(o.x, o.y);
                *(__half2*)(s_x + r * LDX + 128 + c0 + 2) = __floats2half2_rn(o.z, o.w);
            }
        }
        __syncthreads();

        // ================= NODE PATH =================
        gemm64<0, 12>(s_x, LDX, s_w1n, s_b1n, nhalf ? s_g : s_h, LDH, lane, mrow, nhalf * 64);
        __syncwarp();
        if (nhalf == 0) gemm64<0, 4>(s_h, LDH, s_w2n, s_b2n, s_ph, LDP, lane, mrow, 0);
        else            gemm64<1, 4>(s_g, LDH, s_w2n, s_b2n, s_pg, LDP, lane, mrow, 64);
        __syncthreads();

        if (valid) {
            float* vp = out_v + (long)de * 64;
            #pragma unroll
            for (int j = 0; j < 4; ++j) {
                int c0 = l4 * 16 + j * 4;
                float m[4];
                #pragma unroll
                for (int i = 0; i < 4; ++i) {
                    int cc = c0 + i;
                    const float* wr = s_wn + cc * 9;
                    float s = 0.0f;
                    #pragma unroll
                    for (int k = 0; k < 9; ++k) s += s_rbf[r * 10 + k] * wr[k];
                    m[i] = __half2float(s_ph[r * LDP + cc]) *
                           __half2float(s_pg[r * LDP + cc]) * s;
                }
                asm volatile("red.global.add.v4.f32 [%0], {%1,%2,%3,%4};\n"
                             :: "l"(vp + c0), "f"(m[0]), "f"(m[1]), "f"(m[2]), "f"(m[3])
                             : "memory");
            }
        }
        __syncthreads();
    }
}

__global__ void copy_v_init(const float* __restrict__ nf, float* __restrict__ outv, int n4)
{
    for (int i = blockIdx.x * blockDim.x + threadIdx.x; i < n4; i += gridDim.x * blockDim.x)
        ((float4*)outv)[i] = ((const float4*)nf)[i];
}

extern "C" void kernel_launch(void* const* d_in, const int* in_sizes, int n_in,
                              void* d_out, int out_size)
{
    const float* node_feat = (const float*)d_in[0];
    const float* edge_feat = (const float*)d_in[1];
    const float* rbf       = (const float*)d_in[2];
    const int*   src       = (const int*)d_in[3];
    const int*   dst       = (const int*)d_in[4];
    const float* el1w = (const float*)d_in[5];  const float* el1b = (const float*)d_in[6];
    const float* el2w = (const float*)d_in[7];  const float* el2b = (const float*)d_in[8];
    const float* eg1w = (const float*)d_in[9];  const float* eg1b = (const float*)d_in[10];
    const float* eg2w = (const float*)d_in[11]; const float* eg2b = (const float*)d_in[12];
    const float* nl1w = (const float*)d_in[13]; const float* nl1b = (const float*)d_in[14];
    const float* nl2w = (const float*)d_in[15]; const float* nl2b = (const float*)d_in[16];
    const float* ng1w = (const float*)d_in[17]; const float* ng1b = (const float*)d_in[18];
    const float* ng2w = (const float*)d_in[19]; const float* ng2b = (const float*)d_in[20];
    const float* eww  = (const float*)d_in[21]; const float* nww  = (const float*)d_in[22];

    const int E = in_sizes[3];            // src element count
    const int N = in_sizes[0] / 64;       // node count
    float* out_e = (float*)d_out;
    float* out_v = out_e + (size_t)E * 64;

    int sms = 148;
    cudaDeviceGetAttribute(&sms, cudaDevAttrMultiProcessorCount, 0);

    cudaFuncSetAttribute(m3gnet_fused, cudaFuncAttributeMaxDynamicSharedMemorySize, SMEM_BYTES);

    // v_new starts as node_feat; messages are scattered in with atomics.
    copy_v_init<<<sms * 4, 256>>>(node_feat, out_v, N * 16);

    const int ntiles = (E + TILE - 1) / TILE;
    m3gnet_fused<<<sms, THREADS, SMEM_BYTES>>>(
        node_feat, edge_feat, rbf, src, dst,
        el1w, el1b, el2w, el2b, eg1w, eg1b, eg2w, eg2b,
        nl1w, nl1b, nl2w, nl2b, ng1w, ng1b, ng2w, ng2b,
        eww, nww, out_e, out_v, E, ntiles);
}